// round 8
// baseline (speedup 1.0000x reference)
#include <cuda_runtime.h>
#include <cstdint>

#define SIGMA 0.1f
#define BANDS 256
#define KSEL  64
#define B_DIM 128
#define PIX   1024            // 32*32 floats per (b, band)
#define F4_PER_TILE 256       // 1024/4

// Scratch for the selected indices + gate values (alloc-free rule: device globals)
__device__ int   g_idx [KSEL];
__device__ float g_gate[KSEL];

// ---------------------------------------------------------------------------
// Kernel 1: gate computation + top-k selection + ascending-index compaction.
// One block of 256 threads. O(256^2) compares — negligible.
// ---------------------------------------------------------------------------
__global__ void select_kernel(const float* __restrict__ mu,
                              const float* __restrict__ noise,
                              const float* __restrict__ extra)
{
    __shared__ float s_gate[BANDS];
    __shared__ int   s_rank[BANDS];

    int i = threadIdx.x;

    // gate_i = clip(mu + SIGMA*(noise + 0.25*extra) + 0.5, 0, 1)
    float z = mu[i] + SIGMA * (noise[i] + 0.25f * extra[i]);
    float g = z + 0.5f;
    g = fminf(fmaxf(g, 0.0f), 1.0f);
    s_gate[i] = g;
    __syncthreads();

    // rank_i = # of bands strictly better than i (JAX top_k tie-break: lower
    // index wins, so equal value at lower index counts as better).
    int rank = 0;
    #pragma unroll 8
    for (int j = 0; j < BANDS; j++) {
        float gj = s_gate[j];
        rank += (gj > g) || (gj == g && j < i);
    }
    s_rank[i] = rank;
    __syncthreads();

    if (rank < KSEL) {
        // output slot = number of selected bands with smaller index
        int pos = 0;
        for (int j = 0; j < i; j++) pos += (s_rank[j] < KSEL);
        g_idx [pos] = i;
        g_gate[pos] = g;
    }
}

// ---------------------------------------------------------------------------
// Kernel 2: gather + scale. One block per (b, j) pair: contiguous 4 KB read
// from x[b, idx[j], :] -> contiguous 4 KB write to out[b, j, :].
// Pure HBM copy; float4 vectorized.
// ---------------------------------------------------------------------------
__global__ void gather_kernel(const float4* __restrict__ x,
                              float4* __restrict__ out)
{
    int bj = blockIdx.x;          // 0 .. 128*64-1
    int b  = bj >> 6;
    int j  = bj & 63;

    int   band = g_idx[j];
    float g    = g_gate[j];

    const float4* src = x   + (size_t)b * (BANDS * F4_PER_TILE) + (size_t)band * F4_PER_TILE;
    float4*       dst = out + (size_t)bj * F4_PER_TILE;

    float4 v = src[threadIdx.x];
    v.x *= g; v.y *= g; v.z *= g; v.w *= g;
    dst[threadIdx.x] = v;
}

extern "C" void kernel_launch(void* const* d_in, const int* in_sizes, int n_in,
                              void* d_out, int out_size)
{
    const float* x     = (const float*)d_in[0];   // (128,1,256,32,32)
    const float* mu    = (const float*)d_in[1];   // (256,)
    const float* noise = (const float*)d_in[2];   // (256,)
    const float* extra = (const float*)d_in[3];   // (256,)
    // d_in[4] = k (int32 scalar) — fixed at 64 for this problem shape
    (void)in_sizes; (void)n_in; (void)out_size;

    select_kernel<<<1, BANDS>>>(mu, noise, extra);
    gather_kernel<<<B_DIM * KSEL, F4_PER_TILE>>>((const float4*)x, (float4*)d_out);
}

// round 9
// speedup vs baseline: 1.5265x; 1.5265x over previous
#include <cuda_runtime.h>
#include <cstdint>

#define SIGMA 0.1f
#define BANDS 256
#define KSEL  64
#define B_DIM 128
#define F4_PER_TILE 256       // 1024 floats / 4
#define TILES_PER_BLK 4

// Scratch (alloc-free rule: device globals)
__device__ int   g_idx [KSEL];
__device__ float g_gate[KSEL];

// ---------------------------------------------------------------------------
// Kernel 1: gate + top-k + ascending-index compaction. One block, 256 threads.
// ---------------------------------------------------------------------------
__global__ void select_kernel(const float* __restrict__ mu,
                              const float* __restrict__ noise,
                              const float* __restrict__ extra)
{
    __shared__ float    s_gate[BANDS];
    __shared__ unsigned s_ballot[BANDS / 32];

    int i    = threadIdx.x;
    int lane = i & 31;
    int warp = i >> 5;

    // gate_i = clip(mu + SIGMA*(noise + 0.25*extra) + 0.5, 0, 1)
    float z = mu[i] + SIGMA * (noise[i] + 0.25f * extra[i]);
    float g = fminf(fmaxf(z + 0.5f, 0.0f), 1.0f);
    s_gate[i] = g;
    __syncthreads();

    // rank_i = # bands strictly better (JAX top_k tie-break: lower index wins)
    int rank = 0;
    #pragma unroll 8
    for (int j = 0; j < BANDS; j++) {
        float gj = s_gate[j];
        rank += (gj > g) || (gj == g && j < i);
    }

    bool     sel = (rank < KSEL);
    unsigned bal = __ballot_sync(0xffffffffu, sel);
    if (lane == 0) s_ballot[warp] = bal;
    __syncthreads();

    if (sel) {
        // output slot = # selected bands with smaller index (ballot prefix)
        int pos = __popc(bal & ((1u << lane) - 1u));
        #pragma unroll
        for (int w = 0; w < BANDS / 32; w++)
            pos += (w < warp) ? __popc(s_ballot[w]) : 0;
        g_idx [pos] = i;
        g_gate[pos] = g;
    }
}

// ---------------------------------------------------------------------------
// Kernel 2: gather + scale. Each block handles 4 (b,j) tiles; each thread
// performs 4 independent float4 loads (MLP=4), then 4 stores. All accesses
// stay perfectly coalesced (tile = contiguous 4 KB).
// ---------------------------------------------------------------------------
__global__ void gather_kernel(const float4* __restrict__ x,
                              float4* __restrict__ out)
{
#if __CUDA_ARCH__ >= 900
    cudaGridDependencySynchronize();   // PDL: wait for select_kernel's writes
#endif
    int base = blockIdx.x * TILES_PER_BLK;   // first bj index of this block
    int t    = threadIdx.x;

    int   band[TILES_PER_BLK];
    float gv  [TILES_PER_BLK];
    #pragma unroll
    for (int u = 0; u < TILES_PER_BLK; u++) {
        int j   = (base + u) & (KSEL - 1);
        band[u] = g_idx [j];
        gv  [u] = g_gate[j];
    }

    float4 v[TILES_PER_BLK];
    #pragma unroll
    for (int u = 0; u < TILES_PER_BLK; u++) {
        int bj = base + u;
        int b  = bj >> 6;
        v[u] = x[(size_t)(b * BANDS + band[u]) * F4_PER_TILE + t];
    }

    #pragma unroll
    for (int u = 0; u < TILES_PER_BLK; u++) {
        float g = gv[u];
        v[u].x *= g; v[u].y *= g; v[u].z *= g; v[u].w *= g;
        out[(size_t)(base + u) * F4_PER_TILE + t] = v[u];
    }
}

extern "C" void kernel_launch(void* const* d_in, const int* in_sizes, int n_in,
                              void* d_out, int out_size)
{
    const float* x     = (const float*)d_in[0];   // (128,1,256,32,32)
    const float* mu    = (const float*)d_in[1];   // (256,)
    const float* noise = (const float*)d_in[2];   // (256,)
    const float* extra = (const float*)d_in[3];   // (256,)
    (void)in_sizes; (void)n_in; (void)out_size;

    select_kernel<<<1, BANDS>>>(mu, noise, extra);

    // Gather with programmatic dependent launch: starts spinning up while
    // select_kernel finishes; cudaGridDependencySynchronize() in-kernel
    // guarantees g_idx/g_gate visibility.
    cudaLaunchAttribute attr[1];
    attr[0].id = cudaLaunchAttributeProgrammaticStreamSerialization;
    attr[0].val.programmaticStreamSerializationAllowed = 1;

    cudaLaunchConfig_t cfg = {};
    cfg.gridDim  = dim3((B_DIM * KSEL) / TILES_PER_BLK);   // 2048
    cfg.blockDim = dim3(F4_PER_TILE);                      // 256
    cfg.stream   = 0;
    cfg.attrs    = attr;
    cfg.numAttrs = 1;
    cudaLaunchKernelEx(&cfg, gather_kernel, (const float4*)x, (float4*)d_out);
}

// round 10
// speedup vs baseline: 1.5496x; 1.0151x over previous
#include <cuda_runtime.h>
#include <cstdint>

#define SIGMA 0.1f
#define BANDS 256
#define KSEL  64
#define B_DIM 128
#define F4_PER_TILE 256        // 1024 floats / 4
#define TOTAL_TILES (B_DIM * KSEL)   // 8192
#define GATHER_GRID 1184       // 148 SMs * 8 blocks/SM -> one resident wave

// Scratch (alloc-free rule: device globals)
__device__ int   g_idx [KSEL];
__device__ float g_gate[KSEL];

// ---------------------------------------------------------------------------
// Kernel 1: gate + top-k + ascending-index compaction. One block, 256 threads.
// Rank loop vectorized to float4 LDS (64 iters, broadcast = conflict-free).
// ---------------------------------------------------------------------------
__global__ void select_kernel(const float* __restrict__ mu,
                              const float* __restrict__ noise,
                              const float* __restrict__ extra)
{
    __shared__ float    s_gate[BANDS];
    __shared__ unsigned s_ballot[BANDS / 32];

    int i    = threadIdx.x;
    int lane = i & 31;
    int warp = i >> 5;

    // gate_i = clip(mu + SIGMA*(noise + 0.25*extra) + 0.5, 0, 1)
    float z = mu[i] + SIGMA * (noise[i] + 0.25f * extra[i]);
    float g = fminf(fmaxf(z + 0.5f, 0.0f), 1.0f);
    s_gate[i] = g;
    __syncthreads();

    // rank_i = # bands strictly better (JAX top_k tie-break: lower index wins)
    int rank = 0;
    const float4* gate4 = reinterpret_cast<const float4*>(s_gate);
    #pragma unroll 8
    for (int j4 = 0; j4 < BANDS / 4; j4++) {
        float4 gv = gate4[j4];
        int j = j4 * 4;
        rank += (gv.x > g) || (gv.x == g && (j + 0) < i);
        rank += (gv.y > g) || (gv.y == g && (j + 1) < i);
        rank += (gv.z > g) || (gv.z == g && (j + 2) < i);
        rank += (gv.w > g) || (gv.w == g && (j + 3) < i);
    }

    bool     sel = (rank < KSEL);
    unsigned bal = __ballot_sync(0xffffffffu, sel);
    if (lane == 0) s_ballot[warp] = bal;
    __syncthreads();

    if (sel) {
        // output slot = # selected bands with smaller index (ballot prefix)
        int pos = __popc(bal & ((1u << lane) - 1u));
        #pragma unroll
        for (int w = 0; w < BANDS / 32; w++)
            pos += (w < warp) ? __popc(s_ballot[w]) : 0;
        g_idx [pos] = i;
        g_gate[pos] = g;
    }
}

// ---------------------------------------------------------------------------
// Kernel 2: gather + scale. Persistent single-wave grid (1184 blocks),
// grid-stride over (b,j) tiles with a 2-deep software pipeline: next tile's
// load is issued before the current tile's store, so every warp always has a
// load in flight. All accesses are contiguous 4 KB per tile (coalesced).
// ---------------------------------------------------------------------------
__global__ __launch_bounds__(F4_PER_TILE, 8)
void gather_kernel(const float4* __restrict__ x,
                   float4* __restrict__ out)
{
#if __CUDA_ARCH__ >= 900
    cudaGridDependencySynchronize();   // PDL: wait for select_kernel's writes
#endif
    int t      = threadIdx.x;
    int stride = gridDim.x;
    int bj     = blockIdx.x;

    // prologue: load tile bj
    int   j = bj & (KSEL - 1);
    int   b = bj >> 6;
    float4 v = x[(size_t)(b * BANDS + g_idx[j]) * F4_PER_TILE + t];
    float  g = g_gate[j];

    for (int nbj = bj + stride; nbj < TOTAL_TILES; nbj += stride) {
        // issue next tile's load before storing current (MLP across iters)
        int   nj = nbj & (KSEL - 1);
        int   nb = nbj >> 6;
        float4 nv = x[(size_t)(nb * BANDS + g_idx[nj]) * F4_PER_TILE + t];
        float  ng = g_gate[nj];

        v.x *= g; v.y *= g; v.z *= g; v.w *= g;
        out[(size_t)bj * F4_PER_TILE + t] = v;

        v = nv; g = ng; bj = nbj;
    }

    v.x *= g; v.y *= g; v.z *= g; v.w *= g;
    out[(size_t)bj * F4_PER_TILE + t] = v;
}

extern "C" void kernel_launch(void* const* d_in, const int* in_sizes, int n_in,
                              void* d_out, int out_size)
{
    const float* x     = (const float*)d_in[0];   // (128,1,256,32,32)
    const float* mu    = (const float*)d_in[1];   // (256,)
    const float* noise = (const float*)d_in[2];   // (256,)
    const float* extra = (const float*)d_in[3];   // (256,)
    (void)in_sizes; (void)n_in; (void)out_size;

    select_kernel<<<1, BANDS>>>(mu, noise, extra);

    // Gather with programmatic dependent launch: spins up while select_kernel
    // drains; cudaGridDependencySynchronize() guarantees g_idx/g_gate
    // visibility before any gather block reads them.
    cudaLaunchAttribute attr[1];
    attr[0].id = cudaLaunchAttributeProgrammaticStreamSerialization;
    attr[0].val.programmaticStreamSerializationAllowed = 1;

    cudaLaunchConfig_t cfg = {};
    cfg.gridDim  = dim3(GATHER_GRID);
    cfg.blockDim = dim3(F4_PER_TILE);
    cfg.stream   = 0;
    cfg.attrs    = attr;
    cfg.numAttrs = 1;
    cudaLaunchKernelEx(&cfg, gather_kernel, (const float4*)x, (float4*)d_out);
}